// round 8
// baseline (speedup 1.0000x reference)
#include <cuda_runtime.h>
#include <cstdint>

#define NCTA    64
#define COLS    4          // batch columns per CTA (64*4 = 256)
#define NTHR    256
#define HD      256
#define DIM     3
#define LT      20
#define NCLASS  10
#define NSTEPS  380
#define AST     260        // activation column stride (floats)

// packed weights: k4-interleaved [k4][256 rows] float4
// concat: W_in(65 k4, zero-padded K 259->260) | W_h0(64) | W_h1(64) | W_out(64) | Wc1(64)
#define OFFP_IN   0
#define OFFP_H0   (65*256)
#define OFFP_H1   (129*256)
#define OFFP_OUT  (193*256)
#define OFFP_C1   (257*256)
#define NPACK     (321*256)
__device__ float4 g_wpack[NPACK];   // 1.31 MB static scratch (not an allocation)

// ---------------- helpers ----------------
__device__ __forceinline__ float2 ffma2(float2 a, float2 b, float2 c) {
    float2 d;
    asm("fma.rn.f32x2 %0, %1, %2, %3;"
        : "=l"(*(unsigned long long*)&d)
        : "l"(*(unsigned long long*)&a),
          "l"(*(unsigned long long*)&b),
          "l"(*(unsigned long long*)&c));
    return d;
}
__device__ __forceinline__ float lipswish(float x) {
    return 0.909f * x / (1.0f + __expf(-x));
}

// ---------------- repack kernel (runs first; tiny) ----------------
__global__ void repack_kernel(const float* __restrict__ W_in,
                              const float* __restrict__ W_hh,
                              const float* __restrict__ W_out,
                              const float* __restrict__ Wc1) {
    int b = blockIdx.x;       // 0..320 : global k4 index across concatenated matrices
    int r = threadIdx.x;      // row 0..255
    const float* src; int k4; int K; int base;
    if (b < 65)       { src = W_in;          k4 = b;       K = 259; base = OFFP_IN;  }
    else if (b < 129) { src = W_hh;          k4 = b - 65;  K = 256; base = OFFP_H0;  }
    else if (b < 193) { src = W_hh + HD*HD;  k4 = b - 129; K = 256; base = OFFP_H1;  }
    else if (b < 257) { src = W_out;         k4 = b - 193; K = 256; base = OFFP_OUT; }
    else              { src = Wc1;           k4 = b - 257; K = 256; base = OFFP_C1;  }
    float v[4];
#pragma unroll
    for (int i = 0; i < 4; i++) {
        int k = k4 * 4 + i;
        v[i] = (k < K) ? src[r * K + k] : 0.0f;
    }
    g_wpack[base + k4 * 256 + r] = make_float4(v[0], v[1], v[2], v[3]);
}

// ---------------- main kernel ----------------
// dot over one activation column for 4 interleaved rows (r0, r0+64, r0+128, r0+192)
template<int K4>
__device__ __forceinline__ void layer4(const float4* __restrict__ wp,
                                       const float* __restrict__ acol,
                                       int r0, float res[4]) {
    float2 e0 = {0,0}, e1 = {0,0}, e2 = {0,0}, e3 = {0,0};
    float2 o0 = {0,0}, o1 = {0,0}, o2 = {0,0}, o3 = {0,0};
#pragma unroll 4
    for (int k4 = 0; k4 < K4; k4++) {
        float4 av = *(const float4*)(acol + k4 * 4);     // LDS.128 broadcast
        const float4* wk = wp + (k4 << 8) + r0;
        float4 w0 = __ldg(wk);
        float4 w1 = __ldg(wk + 64);
        float4 w2 = __ldg(wk + 128);
        float4 w3 = __ldg(wk + 192);
        float2 ae = make_float2(av.x, av.y), ao = make_float2(av.z, av.w);
        e0 = ffma2(make_float2(w0.x, w0.y), ae, e0); o0 = ffma2(make_float2(w0.z, w0.w), ao, o0);
        e1 = ffma2(make_float2(w1.x, w1.y), ae, e1); o1 = ffma2(make_float2(w1.z, w1.w), ao, o1);
        e2 = ffma2(make_float2(w2.x, w2.y), ae, e2); o2 = ffma2(make_float2(w2.z, w2.w), ao, o2);
        e3 = ffma2(make_float2(w3.x, w3.y), ae, e3); o3 = ffma2(make_float2(w3.z, w3.w), ao, o3);
    }
    res[0] = (e0.x + e0.y) + (o0.x + o0.y);
    res[1] = (e1.x + e1.y) + (o1.x + o1.y);
    res[2] = (e2.x + e2.y) + (o2.x + o2.y);
    res[3] = (e3.x + e3.y) + (o3.x + o3.y);
}

__global__ void __launch_bounds__(NTHR)
ncde_stream(const float* __restrict__ coeffs, const float* __restrict__ times_g,
            const float* __restrict__ W_init, const float* __restrict__ b_init,
            const float* __restrict__ b_in,   const float* __restrict__ b_hh,
            const float* __restrict__ b_out,  const float* __restrict__ bc1,
            const float* __restrict__ Wc2,    const float* __restrict__ bc2,
            float* __restrict__ out) {
    __shared__ float sT[20];
    __shared__ float sB[5][HD];          // b_in, b_h0, b_h1, b_out, bc1
    __shared__ float Z [COLS][AST];      // z (0..255) + x (256..258) + 0 (259)
    __shared__ float A0[COLS][AST];
    __shared__ float A1[COLS][AST];

    const int tid = threadIdx.x;
    const int c   = tid >> 6;            // my column 0..3
    const int r0  = tid & 63;            // base row; rows r0+64j
    const int gb  = blockIdx.x * COLS;   // global batch base

    if (tid < LT) sT[tid] = times_g[tid];
    {
        const float* bs[5] = {b_in, b_hh, b_hh + HD, b_out, bc1};
#pragma unroll
        for (int m = 0; m < 5; m++) sB[m][tid] = bs[m][tid];
    }
    __syncthreads();

    const float tstart = sT[0];
    const float dt = (sT[LT - 1] - tstart) / (float)NSTEPS;
    float t = tstart;

    auto eval_x = [&](int col, float tt) {
        int idx = 0;
#pragma unroll
        for (int i = 1; i <= LT - 2; i++) idx = (sT[i] <= tt) ? i : idx;
        float ta = sT[idx], tb = sT[idx + 1];
        float w = (tt - ta) / (tb - ta), om = 1.0f - w;
        const float* c0 = coeffs + ((gb + col) * LT + idx) * DIM;
        Z[col][256] = c0[0] * om + c0[DIM + 0] * w;
        Z[col][257] = c0[1] * om + c0[DIM + 1] * w;
        Z[col][258] = c0[2] * om + c0[DIM + 2] * w;
        Z[col][259] = 0.0f;
    };

    // ---- x(t0) then z0 = W_init @ x + b_init ----
    if (tid < COLS) eval_x(tid, t);
    __syncthreads();
#pragma unroll
    for (int j = 0; j < 4; j++) {
        int row = r0 + 64 * j;
        float v = __ldg(b_init + row)
                + __ldg(W_init + row*DIM + 0) * Z[c][256]
                + __ldg(W_init + row*DIM + 1) * Z[c][257]
                + __ldg(W_init + row*DIM + 2) * Z[c][258];
        Z[c][row] = v;
    }
    __syncthreads();

    const float4* wpIN  = g_wpack + OFFP_IN;
    const float4* wpH0  = g_wpack + OFFP_H0;
    const float4* wpH1  = g_wpack + OFFP_H1;
    const float4* wpOUT = g_wpack + OFFP_OUT;
    float res[4];

    // ---- main Euler loop: weights streamed from L2, only local syncs ----
    for (int s = 0; s < NSTEPS; s++) {
        // L1: lipswish(W_in @ [z;x] + b_in)
        layer4<65>(wpIN, &Z[c][0], r0, res);
#pragma unroll
        for (int j = 0; j < 4; j++)
            A0[c][r0 + 64*j] = lipswish(res[j] + sB[0][r0 + 64*j]);
        __syncthreads();

        // L2
        layer4<64>(wpH0, &A0[c][0], r0, res);
#pragma unroll
        for (int j = 0; j < 4; j++)
            A1[c][r0 + 64*j] = lipswish(res[j] + sB[1][r0 + 64*j]);
        __syncthreads();

        // L3
        layer4<64>(wpH1, &A1[c][0], r0, res);
#pragma unroll
        for (int j = 0; j < 4; j++)
            A0[c][r0 + 64*j] = lipswish(res[j] + sB[2][r0 + 64*j]);
        __syncthreads();

        // L4: z += dt * tanh(W_out @ h + b_out); also write x(t+dt)
        layer4<64>(wpOUT, &A0[c][0], r0, res);
#pragma unroll
        for (int j = 0; j < 4; j++) {
            int row = r0 + 64*j;
            float f = tanhf(res[j] + sB[3][row]);
            Z[c][row] = fmaf(dt, f, Z[c][row]);
        }
        t = t + dt;
        if (tid < COLS) eval_x(tid, t);
        __syncthreads();
    }

    // ---- classifier: h = relu(Wc1 @ z + bc1) ----
    layer4<64>(g_wpack + OFFP_C1, &Z[c][0], r0, res);
#pragma unroll
    for (int j = 0; j < 4; j++)
        A0[c][r0 + 64*j] = fmaxf(res[j] + sB[4][r0 + 64*j], 0.0f);
    __syncthreads();

    // ---- out = Wc2 @ h + bc2 : 40 dots of 256 ----
    if (tid < COLS * NCLASS) {
        int cc = tid / NCLASS, cls = tid % NCLASS;
        const float* hb = &A0[cc][0];
        const float4* wr = (const float4*)(Wc2 + cls * HD);
        float2 se = {0,0}, so = {0,0};
#pragma unroll 8
        for (int k = 0; k < 64; k++) {
            float4 w = __ldg(wr + k);
            float4 h = *(const float4*)(hb + k*4);
            se = ffma2(make_float2(w.x, w.y), make_float2(h.x, h.y), se);
            so = ffma2(make_float2(w.z, w.w), make_float2(h.z, h.w), so);
        }
        out[(gb + cc) * NCLASS + cls] = __ldg(bc2 + cls) + (se.x + se.y) + (so.x + so.y);
    }
}

// ---------------- launch ----------------
extern "C" void kernel_launch(void* const* d_in, const int* in_sizes, int n_in,
                              void* d_out, int out_size) {
    (void)in_sizes; (void)n_in; (void)out_size;
    const float* coeffs = (const float*)d_in[0];
    const float* times  = (const float*)d_in[1];
    const float* W_init = (const float*)d_in[2];
    const float* b_init = (const float*)d_in[3];
    const float* W_in   = (const float*)d_in[4];
    const float* b_in   = (const float*)d_in[5];
    const float* W_hh   = (const float*)d_in[6];
    const float* b_hh   = (const float*)d_in[7];
    const float* W_out  = (const float*)d_in[8];
    const float* b_out  = (const float*)d_in[9];
    const float* Wc1    = (const float*)d_in[10];
    const float* bc1    = (const float*)d_in[11];
    const float* Wc2    = (const float*)d_in[12];
    const float* bc2    = (const float*)d_in[13];

    repack_kernel<<<321, 256>>>(W_in, W_hh, W_out, Wc1);
    ncde_stream<<<NCTA, NTHR>>>(coeffs, times, W_init, b_init,
                                b_in, b_hh, b_out, bc1, Wc2, bc2,
                                (float*)d_out);
}

// round 9
// speedup vs baseline: 1.5732x; 1.5732x over previous
#include <cuda_runtime.h>
#include <cstdint>

#define NCL     16         // clusters
#define CSZ     8          // CTAs per cluster
#define NBLK    (NCL*CSZ)  // 128 CTAs
#define NTHR    256
#define BPC     16         // batch cols per cluster
#define HD      256
#define DIM     3
#define LT      20
#define NCLASS  10
#define NSTEPS  380
#define ROWS    32
#define MATW    8320       // words per packed matrix: 65 k4 x 32 rows x 4

// ---- smem word offsets ----
#define OFF_W   0                    // [4][65][32][4] = 33280
#define OFF_B   33280                // [4][32]
#define OFF_T   33408                // [20]
#define OFF_MB  33428                // 8 mbarriers (u64) = 16 words (byte 8-aligned)
#define OFF_Z   33448                // [65 k4][16 cols][4] (block 64 = x at init)
#define OFF_H0  (OFF_Z + 65*64)     // [64][16][4]
#define OFF_H1  (OFF_H0 + 64*64)
#define SMEM_WORDS (OFF_H1 + 64*64) // 45800
#define SMEM_BYTES (SMEM_WORDS*4)   // 183200 B

#define MBI(l,g) ((l)*2+(g))         // l: 0=H0(L1) 1=H1(L2) 2=H0(L3) 3=Z(L4); g=col half
#define TXB 8192u                    // 8 CTAs * 256 values * 4B per phase

// ---------------- helpers ----------------
__device__ __forceinline__ float2 ffma2(float2 a, float2 b, float2 c) {
    float2 d;
    asm("fma.rn.f32x2 %0, %1, %2, %3;"
        : "=l"(*(unsigned long long*)&d)
        : "l"(*(unsigned long long*)&a),
          "l"(*(unsigned long long*)&b),
          "l"(*(unsigned long long*)&c));
    return d;
}
__device__ __forceinline__ float lipswish(float x) {
    return 0.909f * x / (1.0f + __expf(-x));
}
__device__ __forceinline__ uint32_t smem_u32(const void* p) {
    uint32_t a;
    asm("{ .reg .u64 t; cvta.to.shared.u64 t, %1; cvt.u32.u64 %0, t; }" : "=r"(a) : "l"(p));
    return a;
}
__device__ __forceinline__ uint32_t mapa_u32(uint32_t a, uint32_t rank) {
    uint32_t d;
    asm("mapa.shared::cluster.u32 %0, %1, %2;" : "=r"(d) : "r"(a), "r"(rank));
    return d;
}
__device__ __forceinline__ void cluster_bar() {
    asm volatile("barrier.cluster.arrive.aligned;" ::: "memory");
    asm volatile("barrier.cluster.wait.aligned;"   ::: "memory");
}
__device__ __forceinline__ void mb_init(uint32_t mb, uint32_t cnt) {
    asm volatile("mbarrier.init.shared.b64 [%0], %1;" :: "r"(mb), "r"(cnt) : "memory");
}
__device__ __forceinline__ void mb_arm(uint32_t mb, uint32_t tx) {
    asm volatile("mbarrier.arrive.expect_tx.shared.b64 _, [%0], %1;" :: "r"(mb), "r"(tx) : "memory");
}
__device__ __forceinline__ void mb_wait(uint32_t mb, uint32_t parity) {
    uint32_t done;
    asm volatile(
        "{\n\t.reg .pred p;\n\t"
        "mbarrier.try_wait.parity.acquire.cta.shared::cta.b64 p, [%1], %2, 0x989680;\n\t"
        "selp.b32 %0, 1, 0, p;\n\t}"
        : "=r"(done) : "r"(mb), "r"(parity) : "memory");
    while (!done) {
        asm volatile(
            "{\n\t.reg .pred p;\n\t"
            "mbarrier.try_wait.parity.acquire.cta.shared::cta.b64 p, [%1], %2, 0x989680;\n\t"
            "selp.b32 %0, 1, 0, p;\n\t}"
            : "=r"(done) : "r"(mb), "r"(parity) : "memory");
    }
}
// send one value to the same slot in all 8 CTAs' smem, feeding barrier mbi
__device__ __forceinline__ void scatter(const uint32_t* __restrict__ pb,
                                        int mbi, uint32_t word_off, float v) {
    uint32_t eoff = word_off * 4u;
    uint32_t moff = (uint32_t)(OFF_MB + mbi * 2) * 4u;
#pragma unroll
    for (int rr = 0; rr < CSZ; rr++) {
        asm volatile(
            "st.async.weak.shared::cluster.mbarrier::complete_tx::bytes.b32 [%0], %1, [%2];"
            :: "r"(pb[rr] + eoff), "f"(v), "r"(pb[rr] + moff) : "memory");
    }
}
// dot over 64 k4: interleaved weights [k4][32r][4] vs interleaved acts [k4][16c][4]
__device__ __forceinline__ float dot_i(const float4* __restrict__ w4,
                                       const float4* __restrict__ a4,
                                       int r, int cI) {
    float2 s0 = {0,0}, s1 = {0,0};
#pragma unroll 8
    for (int k = 0; k < 64; k++) {
        float4 wv = w4[(k << 5) + r];     // 1 wavefront: 4 rows x 16B in one window
        float4 av = a4[(k << 4) + cI];    // 1 wavefront: 8 cols x 16B contiguous
        s0 = ffma2(make_float2(wv.x, wv.y), make_float2(av.x, av.y), s0);
        s1 = ffma2(make_float2(wv.z, wv.w), make_float2(av.z, av.w), s1);
    }
    return (s0.x + s0.y) + (s1.x + s1.y);
}

// ---------------- kernel ----------------
__global__ void __launch_bounds__(NTHR, 1)
ncde_kernel(const float* __restrict__ coeffs, const float* __restrict__ times_g,
            const float* __restrict__ W_init, const float* __restrict__ b_init,
            const float* __restrict__ W_in,   const float* __restrict__ b_in,
            const float* __restrict__ W_hh,   const float* __restrict__ b_hh,
            const float* __restrict__ W_out,  const float* __restrict__ b_out,
            const float* __restrict__ Wc1,    const float* __restrict__ bc1,
            const float* __restrict__ Wc2,    const float* __restrict__ bc2,
            float* __restrict__ out) {
    extern __shared__ float sm[];
    const int tid = threadIdx.x;
    const int cl  = blockIdx.x / CSZ;
    unsigned rank;
    asm("mov.u32 %0, %%cluster_ctarank;" : "=r"(rank));
    const int r  = tid >> 3;             // 0..31 local row
    const int cb = tid & 7;              // col within group
    const int R  = (int)rank * ROWS + r; // global row
    const uint32_t zw = (uint32_t)(((R >> 2) << 6) + (R & 3));  // interleave base for row R
    const int cA = cb, cB = cb + 8;
    const bool lead = (tid == 0);

    const uint32_t smb = smem_u32(sm);
    uint32_t pb[CSZ];
#pragma unroll
    for (int rr = 0; rr < CSZ; rr++) pb[rr] = mapa_u32(smb, rr);
#define MBA(i) (smb + (OFF_MB + (i)*2)*4)

    // ---- repack weights into [k4][32r][4] interleave (zero-padded), biases, times ----
    {
        const float* srcs[4] = {W_in, W_hh, W_hh + HD*HD, W_out};
        const int    kw[4]   = {HD + DIM, HD, HD, HD};
#pragma unroll
        for (int m = 0; m < 4; m++) {
            const float* s = srcs[m];
            const int K = kw[m];
            float* wd = sm + OFF_W + m*MATW;
            for (int idx = tid; idx < ROWS*260; idx += NTHR) {
                int row = idx / 260, k = idx % 260;
                float v = (k < K) ? s[((int)rank*ROWS + row)*K + k] : 0.0f;
                wd[(k >> 2)*128 + row*4 + (k & 3)] = v;
            }
        }
        const float* bs[4] = {b_in, b_hh, b_hh + HD, b_out};
        if (tid < ROWS)
#pragma unroll
            for (int m = 0; m < 4; m++)
                sm[OFF_B + m*ROWS + tid] = bs[m][(int)rank*ROWS + tid];
        if (tid < LT) sm[OFF_T + tid] = times_g[tid];
    }
    if (tid == 0) {
#pragma unroll
        for (int i = 0; i < 8; i++) { mb_init(MBA(i), 1); mb_arm(MBA(i), TXB); }
    }
    __syncthreads();
    cluster_bar();     // all barriers live before any st.async

    const float t0 = sm[OFF_T];
    const float dt = (sm[OFF_T + LT - 1] - t0) / (float)NSTEPS;
    float t = t0;

    auto eval_x = [&](int col, float tt) -> float3 {
        int idx = 0;
#pragma unroll
        for (int i = 1; i <= LT - 2; i++) idx = (sm[OFF_T + i] <= tt) ? i : idx;
        float ta = sm[OFF_T + idx], tb = sm[OFF_T + idx + 1];
        float w = (tt - ta) / (tb - ta), om = 1.0f - w;
        const float* c0 = coeffs + ((cl*BPC + col)*LT + idx)*DIM;
        float3 x;
        x.x = c0[0]*om + c0[DIM+0]*w;
        x.y = c0[1]*om + c0[DIM+1]*w;
        x.z = c0[2]*om + c0[DIM+2]*w;
        return x;
    };

    // ---- z0 = W_init @ x(t0) + b_init, interleaved Z (x staged in Z block 64) ----
    if (tid < BPC) {
        float3 x = eval_x(tid, t);
        sm[OFF_Z + 64*64 + tid*4 + 0] = x.x;
        sm[OFF_Z + 64*64 + tid*4 + 1] = x.y;
        sm[OFF_Z + 64*64 + tid*4 + 2] = x.z;
    }
    __syncthreads();
    for (int i = 0; i < (HD*BPC)/NTHR; i++) {
        int idx = i*NTHR + tid;
        int col = idx & 15, row = idx >> 4;
        const float* xv = sm + OFF_Z + 64*64 + col*4;
        float v = b_init[row]
                + W_init[row*DIM+0]*xv[0]
                + W_init[row*DIM+1]*xv[1]
                + W_init[row*DIM+2]*xv[2];
        sm[OFF_Z + (row >> 2)*64 + col*4 + (row & 3)] = v;
    }
    __syncthreads();

    const float4* w0 = (const float4*)(sm + OFF_W + 0*MATW);
    const float4* w1 = (const float4*)(sm + OFF_W + 1*MATW);
    const float4* w2 = (const float4*)(sm + OFF_W + 2*MATW);
    const float4* w3 = (const float4*)(sm + OFF_W + 3*MATW);
    const float4* aZ  = (const float4*)(sm + OFF_Z);
    const float4* aH0 = (const float4*)(sm + OFF_H0);
    const float4* aH1 = (const float4*)(sm + OFF_H1);
    const float bi0 = sm[OFF_B + 0*ROWS + r];
    const float bi1 = sm[OFF_B + 1*ROWS + r];
    const float bi2 = sm[OFF_B + 2*ROWS + r];
    const float bi3 = sm[OFF_B + 3*ROWS + r];
    // x-tail weights for row r: k = 256..258 -> block 64
    const float wt0 = sm[OFF_W + 64*128 + r*4 + 0];
    const float wt1 = sm[OFF_W + 64*128 + r*4 + 1];
    const float wt2 = sm[OFF_W + 64*128 + r*4 + 2];

    // ---- main Euler loop: R2's proven protocol, 1-wavefront operand loads ----
    for (int s = 0; s < NSTEPS; s++) {
        const uint32_t ph = (uint32_t)(s & 1);
        const uint32_t pz = ph ^ 1u;

        // L1 group A
        if (s) { mb_wait(MBA(MBI(3,0)), pz); if (lead) mb_arm(MBA(MBI(3,0)), TXB); }
        {
            float3 x = eval_x(cA, t);
            float v = dot_i(w0, aZ, r, cA);
            v = lipswish(v + wt0*x.x + wt1*x.y + wt2*x.z + bi0);
            scatter(pb, MBI(0,0), (uint32_t)OFF_H0 + zw + (uint32_t)cA*4, v);
        }
        // L1 group B
        if (s) { mb_wait(MBA(MBI(3,1)), pz); if (lead) mb_arm(MBA(MBI(3,1)), TXB); }
        {
            float3 x = eval_x(cB, t);
            float v = dot_i(w0, aZ, r, cB);
            v = lipswish(v + wt0*x.x + wt1*x.y + wt2*x.z + bi0);
            scatter(pb, MBI(0,1), (uint32_t)OFF_H0 + zw + (uint32_t)cB*4, v);
        }
        // L2
        mb_wait(MBA(MBI(0,0)), ph); if (lead) mb_arm(MBA(MBI(0,0)), TXB);
        scatter(pb, MBI(1,0), (uint32_t)OFF_H1 + zw + (uint32_t)cA*4,
                lipswish(dot_i(w1, aH0, r, cA) + bi1));
        mb_wait(MBA(MBI(0,1)), ph); if (lead) mb_arm(MBA(MBI(0,1)), TXB);
        scatter(pb, MBI(1,1), (uint32_t)OFF_H1 + zw + (uint32_t)cB*4,
                lipswish(dot_i(w1, aH0, r, cB) + bi1));
        // L3 (-> H0 again; safe: full (1,g) barrier proves all CTAs consumed H0)
        mb_wait(MBA(MBI(1,0)), ph); if (lead) mb_arm(MBA(MBI(1,0)), TXB);
        scatter(pb, MBI(2,0), (uint32_t)OFF_H0 + zw + (uint32_t)cA*4,
                lipswish(dot_i(w2, aH1, r, cA) + bi2));
        mb_wait(MBA(MBI(1,1)), ph); if (lead) mb_arm(MBA(MBI(1,1)), TXB);
        scatter(pb, MBI(2,1), (uint32_t)OFF_H0 + zw + (uint32_t)cB*4,
                lipswish(dot_i(w2, aH1, r, cB) + bi2));
        // L4: z += dt * tanh(W_out @ h)
        mb_wait(MBA(MBI(2,0)), ph); if (lead) mb_arm(MBA(MBI(2,0)), TXB);
        {
            float f  = tanhf(dot_i(w3, aH0, r, cA) + bi3);
            float zo = sm[OFF_Z + (int)zw + cA*4];
            scatter(pb, MBI(3,0), (uint32_t)OFF_Z + zw + (uint32_t)cA*4, fmaf(dt, f, zo));
        }
        mb_wait(MBA(MBI(2,1)), ph); if (lead) mb_arm(MBA(MBI(2,1)), TXB);
        {
            float f  = tanhf(dot_i(w3, aH0, r, cB) + bi3);
            float zo = sm[OFF_Z + (int)zw + cB*4];
            scatter(pb, MBI(3,1), (uint32_t)OFF_Z + zw + (uint32_t)cB*4, fmaf(dt, f, zo));
        }
        t = t + dt;
    }

    // ---- final z arrivals (last send at s=379 -> parity 1) ----
    mb_wait(MBA(MBI(3,0)), 1u);
    mb_wait(MBA(MBI(3,1)), 1u);

    // ---- classifier hidden: relu(Wc1 @ z + bc1) -> H0, barriers (0,g), parity 0 ----
    {
        const float4* wg = (const float4*)(Wc1 + R*HD);
        const float bi4 = __ldg(bc1 + R);
#pragma unroll
        for (int g = 0; g < 2; g++) {
            const int c = g*8 + cb;
            float2 s0 = {0,0}, s1 = {0,0};
#pragma unroll 8
            for (int k = 0; k < 64; k++) {
                float4 wv = __ldg(wg + k);
                float4 av = aZ[(k << 4) + c];
                s0 = ffma2(make_float2(wv.x, wv.y), make_float2(av.x, av.y), s0);
                s1 = ffma2(make_float2(wv.z, wv.w), make_float2(av.z, av.w), s1);
            }
            float v = fmaxf((s0.x + s0.y) + (s1.x + s1.y) + bi4, 0.0f);
            scatter(pb, MBI(0,g), (uint32_t)OFF_H0 + zw + (uint32_t)c*4, v);
        }
    }
    mb_wait(MBA(MBI(0,0)), 0u);
    mb_wait(MBA(MBI(0,1)), 0u);

    // ---- out = Wc2 @ h + bc2 (rank 0; 160 items) ----
    if (rank == 0 && tid < BPC*NCLASS) {
        int b = tid / NCLASS, cls = tid % NCLASS;
        const float4* wr = (const float4*)(Wc2 + cls*HD);
        float2 s0 = {0,0}, s1 = {0,0};
#pragma unroll 8
        for (int k = 0; k < 64; k++) {
            float4 w = __ldg(wr + k);
            float4 h = aH0[(k << 4) + b];
            s0 = ffma2(make_float2(w.x, w.y), make_float2(h.x, h.y), s0);
            s1 = ffma2(make_float2(w.z, w.w), make_float2(h.z, h.w), s1);
        }
        out[(cl*BPC + b)*NCLASS + cls] = __ldg(bc2 + cls) + (s0.x + s0.y) + (s1.x + s1.y);
    }

    cluster_bar();   // no CTA exits while peers may still write its smem
}

// ---------------- launch ----------------
extern "C" void kernel_launch(void* const* d_in, const int* in_sizes, int n_in,
                              void* d_out, int out_size) {
    (void)in_sizes; (void)n_in; (void)out_size;
    cudaFuncSetAttribute(ncde_kernel, cudaFuncAttributeMaxDynamicSharedMemorySize, SMEM_BYTES);

    cudaLaunchConfig_t cfg = {};
    cfg.gridDim  = dim3(NBLK, 1, 1);
    cfg.blockDim = dim3(NTHR, 1, 1);
    cfg.dynamicSmemBytes = SMEM_BYTES;
    cfg.stream = 0;

    cudaLaunchAttribute attrs[1];
    attrs[0].id = cudaLaunchAttributeClusterDimension;
    attrs[0].val.clusterDim.x = CSZ;
    attrs[0].val.clusterDim.y = 1;
    attrs[0].val.clusterDim.z = 1;
    cfg.attrs = attrs;
    cfg.numAttrs = 1;

    cudaLaunchKernelEx(&cfg, ncde_kernel,
        (const float*)d_in[0],  (const float*)d_in[1],
        (const float*)d_in[2],  (const float*)d_in[3],
        (const float*)d_in[4],  (const float*)d_in[5],
        (const float*)d_in[6],  (const float*)d_in[7],
        (const float*)d_in[8],  (const float*)d_in[9],
        (const float*)d_in[10], (const float*)d_in[11],
        (const float*)d_in[12], (const float*)d_in[13],
        (float*)d_out);
}